// round 1
// baseline (speedup 1.0000x reference)
#include <cuda_runtime.h>
#include <cstddef>
#include <math.h>

// Problem constants
#define B_  2
#define S_  2048
#define D_  1024
#define H_  16
#define HD_ 64
#define MROWS (B_ * S_)        // 4096
#define QKV_N (3 * D_)         // 3072

// Scratch (device globals: allocation-free)
__device__ float g_qkv[(size_t)MROWS * QKV_N];   // [4096, 3072]
__device__ float g_attn[(size_t)MROWS * D_];     // [4096, 1024]

// ---------------------------------------------------------------------------
// SGEMM:  C[M,N] = A[M,K] * B[N,K]^T + bias[N]
// Tiles: 128x128x16, 256 threads, 8x8 micro-tile per thread.
// Assumes M,N divisible by 128 and K divisible by 16 (true here).
// ---------------------------------------------------------------------------
#define BM 128
#define BN 128
#define BK 16

__global__ void __launch_bounds__(256)
sgemm_bias(const float* __restrict__ A, const float* __restrict__ Bm,
           const float* __restrict__ bias, float* __restrict__ C,
           int M, int N, int K)
{
    __shared__ float As[BK][BM];
    __shared__ float Bs[BK][BN];

    const int tid = threadIdx.x;
    const int tr  = tid >> 4;          // 0..15
    const int tc  = tid & 15;          // 0..15
    const int m0  = blockIdx.y * BM;
    const int n0  = blockIdx.x * BN;

    float acc[8][8];
    #pragma unroll
    for (int i = 0; i < 8; i++)
        #pragma unroll
        for (int j = 0; j < 8; j++) acc[i][j] = 0.f;

    for (int k0 = 0; k0 < K; k0 += BK) {
        // Load 128x16 tiles of A and B (transposed into [k][m]) — 2 float4 each
        #pragma unroll
        for (int it = 0; it < 2; it++) {
            int f    = tid + it * 256;       // 0..511
            int row  = f >> 2;               // 0..127
            int vec  = (f & 3) << 2;         // 0,4,8,12
            float4 av = *(const float4*)&A [(size_t)(m0 + row) * K + k0 + vec];
            float4 bv = *(const float4*)&Bm[(size_t)(n0 + row) * K + k0 + vec];
            As[vec + 0][row] = av.x; As[vec + 1][row] = av.y;
            As[vec + 2][row] = av.z; As[vec + 3][row] = av.w;
            Bs[vec + 0][row] = bv.x; Bs[vec + 1][row] = bv.y;
            Bs[vec + 2][row] = bv.z; Bs[vec + 3][row] = bv.w;
        }
        __syncthreads();

        #pragma unroll
        for (int k = 0; k < BK; k++) {
            float4 a0 = *(const float4*)&As[k][tr * 8];
            float4 a1 = *(const float4*)&As[k][tr * 8 + 4];
            float4 b0 = *(const float4*)&Bs[k][tc * 8];
            float4 b1 = *(const float4*)&Bs[k][tc * 8 + 4];
            float a[8] = {a0.x, a0.y, a0.z, a0.w, a1.x, a1.y, a1.z, a1.w};
            float b[8] = {b0.x, b0.y, b0.z, b0.w, b1.x, b1.y, b1.z, b1.w};
            #pragma unroll
            for (int i = 0; i < 8; i++)
                #pragma unroll
                for (int j = 0; j < 8; j++)
                    acc[i][j] += a[i] * b[j];
        }
        __syncthreads();
    }

    // Epilogue with bias
    #pragma unroll
    for (int i = 0; i < 8; i++) {
        int m = m0 + tr * 8 + i;
        #pragma unroll
        for (int j = 0; j < 8; j += 4) {
            int n = n0 + tc * 8 + j;
            float4 v;
            v.x = acc[i][j + 0] + bias[n + 0];
            v.y = acc[i][j + 1] + bias[n + 1];
            v.z = acc[i][j + 2] + bias[n + 2];
            v.w = acc[i][j + 3] + bias[n + 3];
            *(float4*)&C[(size_t)m * N + n] = v;
        }
    }
}

// ---------------------------------------------------------------------------
// Flash attention (causal), fp32, online softmax with lazy rescale.
// One query row per thread; 128 threads/block; K/V tiles (64x64) in SMEM.
// q pre-scaled by 1/sqrt(HD).
// grid = (S/128, H, B)
// ---------------------------------------------------------------------------
#define TK 64

__global__ void __launch_bounds__(128)
flash_attn(const float* __restrict__ qkv, float* __restrict__ attn)
{
    __shared__ float Ks[TK][HD_];
    __shared__ float Vs[TK][HD_];

    const int tid   = threadIdx.x;
    const int q_blk = blockIdx.x;
    const int h     = blockIdx.y;
    const int b     = blockIdx.z;
    const int q     = q_blk * 128 + tid;          // query position in sequence
    const size_t qrow = (size_t)(b * S_ + q) * QKV_N + (size_t)h * HD_;

    // Load Q row into registers, pre-scaled
    const float scale = 0.125f;  // 1/sqrt(64)
    float4 qr[16];
    {
        const float4* qp = (const float4*)&qkv[qrow];
        #pragma unroll
        for (int i = 0; i < 16; i++) {
            float4 v = qp[i];
            v.x *= scale; v.y *= scale; v.z *= scale; v.w *= scale;
            qr[i] = v;
        }
    }

    float4 o[16];
    #pragma unroll
    for (int i = 0; i < 16; i++) o[i] = make_float4(0.f, 0.f, 0.f, 0.f);
    float m_i = -INFINITY;
    float l_i = 0.f;

    const int kmax = q_blk * 128 + 127;           // last key any thread in block needs
    for (int kt = 0; kt <= kmax; kt += TK) {
        __syncthreads();   // protect previous tile from overwrite
        // Cooperative load of K and V tiles (64 rows x 64 floats each)
        #pragma unroll
        for (int i = 0; i < 8; i++) {
            int f  = tid * 8 + i;                 // 0..1023 float4 slots
            int r  = f >> 4;                      // 0..63
            int c4 = f & 15;                      // 0..15
            size_t base = (size_t)(b * S_ + kt + r) * QKV_N + (size_t)h * HD_;
            ((float4*)Ks[r])[c4] = ((const float4*)&qkv[base + D_    ])[c4];
            ((float4*)Vs[r])[c4] = ((const float4*)&qkv[base + 2 * D_])[c4];
        }
        __syncthreads();

        int jmax = q - kt + 1;
        if (jmax > TK) jmax = TK;
        for (int j = 0; j < jmax; j++) {
            const float4* kr = (const float4*)Ks[j];
            float s = 0.f;
            #pragma unroll
            for (int i = 0; i < 16; i++) {
                float4 k4 = kr[i];
                s += qr[i].x * k4.x + qr[i].y * k4.y +
                     qr[i].z * k4.z + qr[i].w * k4.w;
            }
            if (s > m_i) {
                float alpha = __expf(m_i - s);    // exp(-inf)=0 on first hit
                m_i = s;
                l_i *= alpha;
                #pragma unroll
                for (int i = 0; i < 16; i++) {
                    o[i].x *= alpha; o[i].y *= alpha;
                    o[i].z *= alpha; o[i].w *= alpha;
                }
            }
            float p = __expf(s - m_i);
            l_i += p;
            const float4* vr = (const float4*)Vs[j];
            #pragma unroll
            for (int i = 0; i < 16; i++) {
                float4 v4 = vr[i];
                o[i].x += p * v4.x; o[i].y += p * v4.y;
                o[i].z += p * v4.z; o[i].w += p * v4.w;
            }
        }
    }

    const float inv = 1.f / l_i;
    float4* op = (float4*)&attn[(size_t)(b * S_ + q) * D_ + (size_t)h * HD_];
    #pragma unroll
    for (int i = 0; i < 16; i++) {
        float4 v = o[i];
        v.x *= inv; v.y *= inv; v.z *= inv; v.w *= inv;
        op[i] = v;
    }
}

// ---------------------------------------------------------------------------
// Launch
// ---------------------------------------------------------------------------
extern "C" void kernel_launch(void* const* d_in, const int* in_sizes, int n_in,
                              void* d_out, int out_size)
{
    const float* X     = (const float*)d_in[0];  // [2,2048,1024]
    const float* W_qkv = (const float*)d_in[1];  // [3072,1024]
    const float* b_qkv = (const float*)d_in[2];  // [3072]
    const float* W_out = (const float*)d_in[3];  // [1024,1024]
    const float* b_out = (const float*)d_in[4];  // [1024]
    float* out = (float*)d_out;                  // [2,2048,1024]

    void* qkv_p  = nullptr;
    void* attn_p = nullptr;
    cudaGetSymbolAddress(&qkv_p,  g_qkv);
    cudaGetSymbolAddress(&attn_p, g_attn);
    float* qkv  = (float*)qkv_p;
    float* attn = (float*)attn_p;

    // 1) QKV projection: [4096,3072] = X[4096,1024] @ W_qkv^T + b_qkv
    {
        dim3 grid(QKV_N / BN, MROWS / BM);  // (24, 32)
        sgemm_bias<<<grid, 256>>>(X, W_qkv, b_qkv, qkv, MROWS, QKV_N, D_);
    }

    // 2) Causal flash attention per (batch, head)
    {
        dim3 grid(S_ / 128, H_, B_);        // (16, 16, 2)
        flash_attn<<<grid, 128>>>(qkv, attn);
    }

    // 3) Output projection: out = attn @ W_out^T + b_out
    {
        dim3 grid(D_ / BN, MROWS / BM);     // (8, 32)
        sgemm_bias<<<grid, 256>>>(attn, W_out, b_out, out, MROWS, D_, D_);
    }
}